// round 14
// baseline (speedup 1.0000x reference)
#include <cuda_runtime.h>
#include <math.h>
#include <stdint.h>

#define L_TOT  65536
#define HDIM   256
#define WDIM   256
#define DIM    192
#define C1     48
#define NTOK   8
#define OROW   260   // padded shifted-row length

typedef unsigned long long u64t;

__device__ __forceinline__ u64t ffma2(u64t a, u64t b, u64t c) {
    u64t d;
    asm("fma.rn.f32x2 %0, %1, %2, %3;" : "=l"(d) : "l"(a), "l"(b), "l"(c));
    return d;
}
union F2u { u64t u; float2 f; };
__device__ __forceinline__ float lohi_sum(u64t v) { F2u t; t.u = v; return t.f.x + t.f.y; }
__device__ __forceinline__ float lo_of(u64t v) { F2u t; t.u = v; return t.f.x; }
__device__ __forceinline__ float hi_of(u64t v) { F2u t; t.u = v; return t.f.y; }

// ---------------- scratch ----------------
__device__ float  g_intensity[L_TOT];
__device__ float  g_f1[(size_t)C1 * L_TOT];          // conv1 out [ic][l] (E rows)
__device__ float  g_f1o[(size_t)C1 * HDIM * OROW];   // conv1 out shifted rows, pads 0
__device__ float  g_feat[(size_t)L_TOT * DIM];       // conv2 out [l][c]
__device__ float  g_gamma[L_TOT];
__device__ float  g_beta[L_TOT];
// conv2 dup weights, paired layout: [((ic*9+kp)*3+g)][pair(2)][tx(16)][jj(2)], oc=g*64+tx+16*(2*pair+jj)
__device__ float2 g_w2d[432 * 192];
// out_w k-pairs, paired layout: [((kc*16+kp)*6+pair)][tx(16)][jj(2)], o=tx+16*(2*pair+jj)
__device__ float2 g_owt[96 * 192];
// route1_w k-pairs, paired layout: [((kc*32+kp)*3+pair)][tx(16)][jj(2)]
__device__ float2 g_r1t[96 * 96];

// ---------------- K0: weight prep ----------------
__global__ void k_prep(const float* __restrict__ w2, const float* __restrict__ out_w,
                       const float* __restrict__ w1) {
    int idx = blockIdx.x * 256 + threadIdx.x;
    if (idx < 82944) {
        int lane = idx & 63, chunk = idx >> 6;
        int g = chunk % 3, t2 = chunk / 3;
        int kp = t2 % 9, ic = t2 / 9;
        int pair = lane >> 5, r = lane & 31;
        int tx = r >> 1, jj = r & 1;
        int oc = g * 64 + tx + 16 * (2 * pair + jj);
        float w = w2[(size_t)oc * 432 + ic * 9 + kp];
        g_w2d[idx] = make_float2(w, w);
    } else if (idx < 101376) {
        int j = idx - 82944;
        int lane = j & 31, t = j >> 5;
        int tx = lane >> 1, jj = lane & 1;
        int pair = t % 6, t2 = t / 6;
        int kp = t2 % 16, kc = t2 / 16;
        int o = tx + 16 * (2 * pair + jj);
        int kk = kc * 32 + kp * 2;
        g_owt[j] = make_float2(out_w[o * DIM + kk], out_w[o * DIM + kk + 1]);
    } else {
        int j = idx - 101376;
        if (j < 9216) {
            int lane = j & 31, t = j >> 5;
            int tx = lane >> 1, jj = lane & 1;
            int pair = t % 3, t2 = t / 3;
            int kp = t2 % 32, kc = t2 / 32;
            int o = tx + 16 * (2 * pair + jj);
            int kk = kc * 64 + kp * 2;
            g_r1t[j] = make_float2(w1[o * DIM + kk], w1[o * DIM + kk + 1]);
        }
    }
}

// ---------------- K1: intensity ----------------
__global__ void k_intensity(const float* __restrict__ x) {
    int l = blockIdx.x * 256 + threadIdx.x;
    const float* p = x + (size_t)l * DIM;
    g_intensity[l] = 0.299f * p[0] + 0.587f * p[1] + 0.114f * p[2];
}

// ---------------- K2: conv1 1->48, 3x3 SAME, LeakyReLU(0.2) ----------------
__global__ void k_conv1(const float* __restrict__ w, const float* __restrict__ b) {
    int l  = blockIdx.x * 256 + threadIdx.x;
    int oc = blockIdx.y;
    int y = l >> 8, xx = l & 255;
    float acc = b[oc];
    #pragma unroll
    for (int ky = 0; ky < 3; ky++) {
        int gy = y + ky - 1;
        if (gy < 0 || gy >= HDIM) continue;
        #pragma unroll
        for (int kx = 0; kx < 3; kx++) {
            int gx = xx + kx - 1;
            if (gx < 0 || gx >= WDIM) continue;
            acc += w[oc * 9 + ky * 3 + kx] * g_intensity[(gy << 8) + gx];
        }
    }
    acc = (acc > 0.f) ? acc : 0.2f * acc;
    g_f1[(size_t)oc * L_TOT + l] = acc;
    g_f1o[((size_t)oc * HDIM + y) * OROW + xx + 1] = acc;
}

// ---------------- K3: conv2 48->192 (pixel-pair f32x2, 512 thr, high occ) --------
// Block: 128 pix x 64 oc, 512 thr (tx 0..15 oc-lanes, ty 0..31 pair-groups).
// Thread: 2 pix-pairs x 4 oc -> acc 16 regs, ~55 regs total, 2 CTAs = 32 warps/SM.
__global__ __launch_bounds__(512, 2) void k_conv2(const float* __restrict__ b2) {
    __shared__ __align__(16) float  Ps[2][2][3][264];  // [grp-buf][u][row][E|pad|O]
    __shared__ __align__(16) float2 Ws[2][2][9][64];   // paired layout per kp
    int tid = threadIdx.x;
    int bid = blockIdx.x;
    int oc0  = (bid % 3) * 64;
    int q    = bid / 3;
    int half = q & 1;
    int y    = q >> 1;
    int x0   = half << 7;
    int tx = tid & 15;   // oc lane: oc = oc0 + tx + 16*j
    int ty = tid >> 4;   // 0..31: pairs 2*ty + i, i<2

    u64t acc[2][4];
    #pragma unroll
    for (int i = 0; i < 2; i++)
        #pragma unroll
        for (int j = 0; j < 4; j++) acc[i][j] = 0ull;

    const float4 zero4 = make_float4(0.f, 0.f, 0.f, 0.f);
    int gsel = bid % 3;

    auto stage = [&](int g, int buf) {
        #pragma unroll
        for (int u = 0; u < 2; u++) {
            int ic = g * 2 + u;
            for (int idx = tid; idx < 288; idx += 512) {
                int kp = idx >> 5, t = idx & 31;
                ((float4*)&Ws[buf][u][kp][0])[t] =
                    ((const float4*)&g_w2d[((ic * 9 + kp) * 3 + gsel) * 64])[t];
            }
            for (int idx = tid; idx < 195; idx += 512) {
                int r = idx / 65, c = idx - r * 65;
                int gy = y + r - 1;
                float4 v = zero4;
                int dst;
                if (c < 32) {
                    if (gy >= 0 && gy < HDIM)
                        v = *(const float4*)&g_f1[((size_t)ic * HDIM + gy) * WDIM + x0 + c * 4];
                    dst = c * 4;
                } else {
                    int co = c - 32;
                    if (gy >= 0 && gy < HDIM)
                        v = *(const float4*)&g_f1o[((size_t)ic * HDIM + gy) * OROW + x0 + co * 4];
                    dst = 132 + co * 4;
                }
                *(float4*)&Ps[buf][u][r][dst] = v;
            }
        }
    };

    stage(0, 0);
    __syncthreads();
    for (int g = 0; g < 24; g++) {
        int buf = g & 1;
        if (g + 1 < 24) stage(g + 1, buf ^ 1);
        #pragma unroll
        for (int u = 0; u < 2; u++) {
            #pragma unroll
            for (int ky = 0; ky < 3; ky++) {
                const float* E = &Ps[buf][u][ky][0];
                const float* O = E + 132;
                #pragma unroll
                for (int kx = 0; kx < 3; kx++) {
                    int kp = ky * 3 + kx;
                    const ulonglong2* wp = (const ulonglong2*)&Ws[buf][u][kp][0];
                    ulonglong2 w01 = wp[tx];
                    ulonglong2 w23 = wp[16 + tx];
                    u64t bv[4] = {w01.x, w01.y, w23.x, w23.y};
                    const float* ap = (kx == 1) ? E : O;
                    int ofs = (kx == 2) ? 2 : 0;
                    #pragma unroll
                    for (int i = 0; i < 2; i++) {
                        u64t a = *(const u64t*)&ap[(ty * 2 + i) * 2 + ofs];
                        #pragma unroll
                        for (int j = 0; j < 4; j++)
                            acc[i][j] = ffma2(a, bv[j], acc[i][j]);
                    }
                }
            }
        }
        __syncthreads();
    }

    float bj[4];
    #pragma unroll
    for (int j = 0; j < 4; j++) bj[j] = b2[oc0 + tx + 16 * j];
    #pragma unroll
    for (int i = 0; i < 2; i++) {
        int p = (ty * 2 + i) * 2;
        int l = (y << 8) + x0 + p;
        float* op0 = g_feat + (size_t)l * DIM + oc0;
        float* op1 = op0 + DIM;
        #pragma unroll
        for (int j = 0; j < 4; j++) {
            op0[tx + 16 * j] = lo_of(acc[i][j]) + bj[j];
            op1[tx + 16 * j] = hi_of(acc[i][j]) + bj[j];
        }
    }
}

// ---------------- K4: routing MLP (FFMA2 k-pair, LDS.128 b) + gumbel argmax ------
__global__ __launch_bounds__(256, 2) void k_route(const float* __restrict__ x,
                                                  const float* __restrict__ b1,
                                                  const float* __restrict__ w2,
                                                  const float* __restrict__ b2r,
                                                  const float* __restrict__ gumbel,
                                                  const float* __restrict__ emb) {
    extern __shared__ float sh[];
    float* z_s  = sh;                       // [64][196]
    u64t*  W1p  = (u64t*)(sh + 12544);      // [32][96] paired layout
    float* hm_s = sh + 12544 + 6144;        // [64][100]
    float* W2s  = sh + 25088;               // [768]
    float* lg_s = sh + 25856;               // [64][9]

    int tid = threadIdx.x;
    int l0 = blockIdx.x * 64;
    int tx = tid & 15;
    int ty = tid >> 4;

    const float4* x4 = (const float4*)(x + (size_t)l0 * DIM);
    const float4* f4 = (const float4*)(g_feat + (size_t)l0 * DIM);
    for (int idx = tid; idx < 3072; idx += 256) {
        int tok = idx / 48, c4 = idx % 48;
        float4 xv = x4[tok * 48 + c4];
        float4 fv = f4[tok * 48 + c4];
        float4 z;
        z.x = xv.x + 0.3f * fv.x; z.y = xv.y + 0.3f * fv.y;
        z.z = xv.z + 0.3f * fv.z; z.w = xv.w + 0.3f * fv.w;
        *(float4*)&z_s[tok * 196 + c4 * 4] = z;
    }
    for (int idx = tid; idx < 768; idx += 256) W2s[idx] = w2[idx];

    u64t acc[4][6];
    #pragma unroll
    for (int i = 0; i < 4; i++)
        #pragma unroll
        for (int j = 0; j < 6; j++) acc[i][j] = 0ull;

    for (int kc = 0; kc < 3; kc++) {
        __syncthreads();
        for (int idx = tid; idx < 3072; idx += 256)
            W1p[idx] = ((const u64t*)g_r1t)[kc * 3072 + idx];
        __syncthreads();
        #pragma unroll 4
        for (int kp = 0; kp < 32; kp++) {
            u64t a[4];
            #pragma unroll
            for (int i = 0; i < 4; i++)
                a[i] = *(const u64t*)&z_s[(ty * 4 + i) * 196 + kc * 64 + kp * 2];
            const ulonglong2* wp = (const ulonglong2*)&W1p[kp * 96];
            u64t bv[6];
            #pragma unroll
            for (int p = 0; p < 3; p++) {
                ulonglong2 w = wp[p * 16 + tx];
                bv[2 * p] = w.x; bv[2 * p + 1] = w.y;
            }
            #pragma unroll
            for (int j = 0; j < 6; j++)
                #pragma unroll
                for (int i = 0; i < 4; i++)
                    acc[i][j] = ffma2(a[i], bv[j], acc[i][j]);
        }
    }
    __syncthreads();
    #pragma unroll
    for (int j = 0; j < 6; j++) {
        float bb = b1[tx + 16 * j];
        #pragma unroll
        for (int i = 0; i < 4; i++) {
            float v = lohi_sum(acc[i][j]) + bb;
            v = 0.5f * v * (1.0f + erff(v * 0.7071067811865476f));
            hm_s[(ty * 4 + i) * 100 + tx + 16 * j] = v;
        }
    }
    __syncthreads();
    #pragma unroll
    for (int half = 0; half < 2; half++) {
        int tok = (tid >> 3) + half * 32;
        int t = tid & 7;
        float s = b2r[t];
        const float4* hp = (const float4*)&hm_s[tok * 100];
        const float4* wp = (const float4*)&W2s[t * 96];
        #pragma unroll 6
        for (int j4 = 0; j4 < 24; j4++) {
            float4 h = hp[j4], w = wp[j4];
            s += h.x * w.x + h.y * w.y + h.z * w.z + h.w * w.w;
        }
        lg_s[tok * 9 + t] = s;
    }
    __syncthreads();
    if (tid < 64) {
        int tok = tid;
        int l = l0 + tok;
        float mx = -1e30f;
        #pragma unroll
        for (int t = 0; t < NTOK; t++) mx = fmaxf(mx, lg_s[tok * 9 + t]);
        float e[NTOK], sum = 0.f;
        #pragma unroll
        for (int t = 0; t < NTOK; t++) { e[t] = expf(lg_s[tok * 9 + t] - mx); sum += e[t]; }
        float inv = 1.0f / sum;
        float inten = g_intensity[l];
        float best = -1e30f; int kbest = 0; float rw0 = 0.f;
        #pragma unroll
        for (int t = 0; t < NTOK; t++) {
            float rw = e[t] * inv;
            if (t == 0) rw0 = rw;
            float sim = 1.0f - fabsf(emb[t] - inten);
            float u = gumbel[(size_t)l * NTOK + t];
            u = fmaxf(u, 1e-10f);
            float g = -logf(-logf(u));
            float sc = rw * sim + g;
            if (sc > best) { best = sc; kbest = t; }
        }
        float ek = emb[kbest];
        g_gamma[l] = 0.3f + 0.7f / (1.0f + expf(-ek));
        g_beta[l]  = rw0 - 0.5f;
    }
}

// ---------------- K5: v=D*(gamma*x+beta), LayerNorm, out (LDS.128 b) -------------
__global__ __launch_bounds__(256, 2) void k_final(const float* __restrict__ x,
                                                  const float* __restrict__ Dv,
                                                  const float* __restrict__ ln_w,
                                                  const float* __restrict__ ln_b,
                                                  const float* __restrict__ out_b,
                                                  float* __restrict__ out) {
    extern __shared__ float sh[];
    float*  v_s  = sh;                           // [64][196]
    u64t*   Bs   = (u64t*)(sh + 64 * 196);       // [16][192] paired layout
    float*  mu_s = sh + 64 * 196 + 16 * 192 * 2; // [64]
    float*  rs_s = mu_s + 64;                    // [64]

    int tid = threadIdx.x;
    int l0 = blockIdx.x * 64;
    int tx = tid & 15;
    int ty = tid >> 4;

    for (int idx = tid; idx < 3072; idx += 256) {
        int tok = idx / 48, c4 = idx % 48;
        int l = l0 + tok;
        float4 xv = *(const float4*)&x[(size_t)l * DIM + c4 * 4];
        float4 dv = *(const float4*)&Dv[c4 * 4];
        float g = g_gamma[l], b = g_beta[l];
        float4 v;
        v.x = dv.x * (g * xv.x + b); v.y = dv.y * (g * xv.y + b);
        v.z = dv.z * (g * xv.z + b); v.w = dv.w * (g * xv.w + b);
        *(float4*)&v_s[tok * 196 + c4 * 4] = v;
    }
    __syncthreads();
    {
        int tok = tid >> 2, l4 = tid & 3;
        float s = 0.f, sq = 0.f;
        for (int c = l4; c < DIM; c += 4) {
            float v = v_s[tok * 196 + c];
            s += v; sq += v * v;
        }
        s  += __shfl_down_sync(0xffffffffu, s, 2);
        sq += __shfl_down_sync(0xffffffffu, sq, 2);
        s  += __shfl_down_sync(0xffffffffu, s, 1);
        sq += __shfl_down_sync(0xffffffffu, sq, 1);
        if (l4 == 0) {
            float mu = s * (1.0f / DIM);
            float var = sq * (1.0f / DIM) - mu * mu;
            mu_s[tok] = mu;
            rs_s[tok] = rsqrtf(var + 1e-5f);
        }
    }
    __syncthreads();
    for (int idx = tid; idx < 3072; idx += 256) {
        int tok = idx / 48, c4 = idx % 48;
        float4 v = *(const float4*)&v_s[tok * 196 + c4 * 4];
        float4 lw = *(const float4*)&ln_w[c4 * 4];
        float4 lb = *(const float4*)&ln_b[c4 * 4];
        float mu = mu_s[tok], rs = rs_s[tok];
        v.x = (v.x - mu) * rs * lw.x + lb.x; v.y = (v.y - mu) * rs * lw.y + lb.y;
        v.z = (v.z - mu) * rs * lw.z + lb.z; v.w = (v.w - mu) * rs * lw.w + lb.w;
        *(float4*)&v_s[tok * 196 + c4 * 4] = v;
    }

    u64t acc[4][12];
    #pragma unroll
    for (int i = 0; i < 4; i++)
        #pragma unroll
        for (int j = 0; j < 12; j++) acc[i][j] = 0ull;

    for (int kc = 0; kc < 6; kc++) {
        __syncthreads();
        for (int idx = tid; idx < 3072; idx += 256)
            Bs[idx] = ((const u64t*)g_owt)[kc * 3072 + idx];
        __syncthreads();
        #pragma unroll
        for (int kp = 0; kp < 16; kp++) {
            u64t a[4];
            #pragma unroll
            for (int i = 0; i < 4; i++)
                a[i] = *(const u64t*)&v_s[(ty * 4 + i) * 196 + kc * 32 + kp * 2];
            const ulonglong2* wp = (const ulonglong2*)&Bs[kp * 192];
            u64t bv[12];
            #pragma unroll
            for (int p = 0; p < 6; p++) {
                ulonglong2 w = wp[p * 16 + tx];
                bv[2 * p] = w.x; bv[2 * p + 1] = w.y;
            }
            #pragma unroll
            for (int j = 0; j < 12; j++)
                #pragma unroll
                for (int i = 0; i < 4; i++)
                    acc[i][j] = ffma2(a[i], bv[j], acc[i][j]);
        }
    }

    float bb[12];
    #pragma unroll
    for (int j = 0; j < 12; j++) bb[j] = out_b[tx + 16 * j];
    #pragma unroll
    for (int i = 0; i < 4; i++) {
        int l = l0 + ty * 4 + i;
        float* op = out + (size_t)l * DIM;
        #pragma unroll
        for (int j = 0; j < 12; j++)
            op[tx + 16 * j] = lohi_sum(acc[i][j]) + bb[j];
    }
}

// ---------------- launch ----------------
extern "C" void kernel_launch(void* const* d_in, const int* in_sizes, int n_in,
                              void* d_out, int out_size) {
    const float* x        = (const float*)d_in[0];
    const float* gumbel_u = (const float*)d_in[1];
    const float* conv1_w  = (const float*)d_in[2];
    const float* conv1_b  = (const float*)d_in[3];
    const float* conv2_w  = (const float*)d_in[4];
    const float* conv2_b  = (const float*)d_in[5];
    const float* route1_w = (const float*)d_in[6];
    const float* route1_b = (const float*)d_in[7];
    const float* route2_w = (const float*)d_in[8];
    const float* route2_b = (const float*)d_in[9];
    const float* Dv       = (const float*)d_in[11];
    const float* ln_w     = (const float*)d_in[12];
    const float* ln_b     = (const float*)d_in[13];
    const float* out_w    = (const float*)d_in[14];
    const float* out_b    = (const float*)d_in[15];
    const float* emb      = (const float*)d_in[16];
    float* out = (float*)d_out;

    int route_smem = (25856 + 576 + 32) * (int)sizeof(float);
    int final_smem = (64 * 196 + 16 * 192 * 2 + 128 + 16) * (int)sizeof(float);
    static int attr_done = 0;
    if (!attr_done) {
        cudaFuncSetAttribute(k_route, cudaFuncAttributeMaxDynamicSharedMemorySize, route_smem);
        cudaFuncSetAttribute(k_final, cudaFuncAttributeMaxDynamicSharedMemorySize, final_smem);
        attr_done = 1;
    }

    k_prep<<<(82944 + 18432 + 9216 + 255) / 256, 256>>>(conv2_w, out_w, route1_w);
    k_intensity<<<L_TOT / 256, 256>>>(x);
    k_conv1<<<dim3(L_TOT / 256, C1), 256>>>(conv1_w, conv1_b);
    k_conv2<<<6 * HDIM, 512>>>(conv2_b);
    k_route<<<L_TOT / 64, 256, route_smem>>>(x, route1_b, route2_w, route2_b,
                                             gumbel_u, emb);
    k_final<<<L_TOT / 64, 256, final_smem>>>(x, Dv, ln_w, ln_b, out_b, out);
}

// round 17
// speedup vs baseline: 1.1261x; 1.1261x over previous
#include <cuda_runtime.h>
#include <math.h>
#include <stdint.h>

#define L_TOT  65536
#define HDIM   256
#define WDIM   256
#define DIM    192
#define C1     48
#define NTOK   8
#define OROW   260   // padded shifted-row length (O copy: v(q-1))
#define QROW   256   // Q copy: v(q+1), pad at q=255

typedef unsigned long long u64t;

__device__ __forceinline__ u64t ffma2(u64t a, u64t b, u64t c) {
    u64t d;
    asm("fma.rn.f32x2 %0, %1, %2, %3;" : "=l"(d) : "l"(a), "l"(b), "l"(c));
    return d;
}
union F2u { u64t u; float2 f; };
__device__ __forceinline__ float lohi_sum(u64t v) { F2u t; t.u = v; return t.f.x + t.f.y; }
__device__ __forceinline__ float lo_of(u64t v) { F2u t; t.u = v; return t.f.x; }
__device__ __forceinline__ float hi_of(u64t v) { F2u t; t.u = v; return t.f.y; }

// ---------------- scratch ----------------
__device__ float  g_intensity[L_TOT];
__device__ float  g_f1[(size_t)C1 * L_TOT];          // conv1 out [ic][l] (E rows)
__device__ float  g_f1o[(size_t)C1 * HDIM * OROW];   // shifted rows v(q-1), pads 0
__device__ float  g_f1q[(size_t)C1 * HDIM * QROW];   // shifted rows v(q+1), pads 0
__device__ float  g_feat[(size_t)L_TOT * DIM];       // conv2 out [l][c]
__device__ float  g_gamma[L_TOT];
__device__ float  g_beta[L_TOT];
// conv2 dup weights, paired layout: [((ic*9+kp)*3+g)][pair(2)][tx(16)][jj(2)]
__device__ float2 g_w2d[432 * 192];
// out_w k-pairs, paired layout: [((kc*16+kp)*6+pair)][tx(16)][jj(2)]
__device__ float2 g_owt[96 * 192];
// route1_w k-pairs, paired layout: [((kc*32+kp)*3+pair)][tx(16)][jj(2)]
__device__ float2 g_r1t[96 * 96];

// ---------------- K0: weight prep ----------------
__global__ void k_prep(const float* __restrict__ w2, const float* __restrict__ out_w,
                       const float* __restrict__ w1) {
    int idx = blockIdx.x * 256 + threadIdx.x;
    if (idx < 82944) {
        int lane = idx & 63, chunk = idx >> 6;
        int g = chunk % 3, t2 = chunk / 3;
        int kp = t2 % 9, ic = t2 / 9;
        int pair = lane >> 5, r = lane & 31;
        int tx = r >> 1, jj = r & 1;
        int oc = g * 64 + tx + 16 * (2 * pair + jj);
        float w = w2[(size_t)oc * 432 + ic * 9 + kp];
        g_w2d[idx] = make_float2(w, w);
    } else if (idx < 101376) {
        int j = idx - 82944;
        int lane = j & 31, t = j >> 5;
        int tx = lane >> 1, jj = lane & 1;
        int pair = t % 6, t2 = t / 6;
        int kp = t2 % 16, kc = t2 / 16;
        int o = tx + 16 * (2 * pair + jj);
        int kk = kc * 32 + kp * 2;
        g_owt[j] = make_float2(out_w[o * DIM + kk], out_w[o * DIM + kk + 1]);
    } else {
        int j = idx - 101376;
        if (j < 9216) {
            int lane = j & 31, t = j >> 5;
            int tx = lane >> 1, jj = lane & 1;
            int pair = t % 3, t2 = t / 3;
            int kp = t2 % 32, kc = t2 / 32;
            int o = tx + 16 * (2 * pair + jj);
            int kk = kc * 64 + kp * 2;
            g_r1t[j] = make_float2(w1[o * DIM + kk], w1[o * DIM + kk + 1]);
        }
    }
}

// ---------------- K1: intensity ----------------
__global__ void k_intensity(const float* __restrict__ x) {
    int l = blockIdx.x * 256 + threadIdx.x;
    const float* p = x + (size_t)l * DIM;
    g_intensity[l] = 0.299f * p[0] + 0.587f * p[1] + 0.114f * p[2];
}

// ---------------- K2: conv1 1->48, 3x3 SAME, LeakyReLU(0.2) ----------------
__global__ void k_conv1(const float* __restrict__ w, const float* __restrict__ b) {
    int l  = blockIdx.x * 256 + threadIdx.x;
    int oc = blockIdx.y;
    int y = l >> 8, xx = l & 255;
    float acc = b[oc];
    #pragma unroll
    for (int ky = 0; ky < 3; ky++) {
        int gy = y + ky - 1;
        if (gy < 0 || gy >= HDIM) continue;
        #pragma unroll
        for (int kx = 0; kx < 3; kx++) {
            int gx = xx + kx - 1;
            if (gx < 0 || gx >= WDIM) continue;
            acc += w[oc * 9 + ky * 3 + kx] * g_intensity[(gy << 8) + gx];
        }
    }
    acc = (acc > 0.f) ? acc : 0.2f * acc;
    g_f1[(size_t)oc * L_TOT + l] = acc;
    g_f1o[((size_t)oc * HDIM + y) * OROW + xx + 1] = acc;          // O[q]=v(q-1)
    if (xx > 0)
        g_f1q[((size_t)oc * HDIM + y) * QROW + xx - 1] = acc;      // Q[q]=v(q+1)
}

// ---------------- K3: conv2 48->192 (8 pix-pairs x 4 oc, E/O/Q aligned copies) ----
// Block: 256 pix (full row) x 64 oc, 256 thr. Per tap: 4 a-LDS.128 + 2 b-LDS.128 +
// 32 ffma2 (64 MACs) -> 1.5 smem B/MAC. Double-buffered 2-ic groups, 24 syncs.
__global__ __launch_bounds__(256, 2) void k_conv2(const float* __restrict__ b2) {
    __shared__ __align__(16) float  Ps[2][2][3][768];  // [buf][u][row][E|O|Q], 256 each
    __shared__ __align__(16) float2 Ws[2][2][9][64];
    int tid = threadIdx.x;
    int bid = blockIdx.x;
    int gsel = bid % 3;
    int oc0  = gsel * 64;
    int y    = bid / 3;
    int tx = tid & 15;   // oc lane: oc = oc0 + tx + 16*j
    int ty = tid >> 4;   // pair group: pairs ty*8 + 0..7

    u64t acc[8][4];
    #pragma unroll
    for (int i = 0; i < 8; i++)
        #pragma unroll
        for (int j = 0; j < 4; j++) acc[i][j] = 0ull;

    const float4 zero4 = make_float4(0.f, 0.f, 0.f, 0.f);

    // staging: 144 weight float4 + 576 pixel float4 per 2-ic group, all aligned copies
    auto stage = [&](int g, int buf) {
        #pragma unroll
        for (int u = 0; u < 2; u++) {
            int ic = g * 2 + u;
            for (int idx = tid; idx < 144; idx += 256) {
                int kp = idx >> 4, t = idx & 15;
                ((float4*)&Ws[buf][u][kp][0])[t] =
                    ((const float4*)&g_w2d[((ic * 9 + kp) * 3 + gsel) * 64])[t];
            }
            for (int idx = tid; idx < 576; idx += 256) {
                int r = idx / 192, rem = idx - r * 192;
                int cp = rem >> 6, t = rem & 63;
                int gy = y + r - 1;
                float4 v = zero4;
                if (gy >= 0 && gy < HDIM) {
                    if (cp == 0)
                        v = *(const float4*)&g_f1[((size_t)ic * HDIM + gy) * WDIM + t * 4];
                    else if (cp == 1)
                        v = *(const float4*)&g_f1o[((size_t)ic * HDIM + gy) * OROW + t * 4];
                    else
                        v = *(const float4*)&g_f1q[((size_t)ic * HDIM + gy) * QROW + t * 4];
                }
                *(float4*)&Ps[buf][u][r][cp * 256 + t * 4] = v;
            }
        }
    };

    stage(0, 0);
    __syncthreads();
    for (int g = 0; g < 24; g++) {
        int buf = g & 1;
        if (g + 1 < 24) stage(g + 1, buf ^ 1);
        #pragma unroll
        for (int u = 0; u < 2; u++) {
            #pragma unroll
            for (int ky = 0; ky < 3; ky++) {
                const float* R = &Ps[buf][u][ky][0];
                #pragma unroll
                for (int kx = 0; kx < 3; kx++) {
                    int kp = ky * 3 + kx;
                    const ulonglong2* wp = (const ulonglong2*)&Ws[buf][u][kp][0];
                    ulonglong2 w01 = wp[tx];
                    ulonglong2 w23 = wp[16 + tx];
                    u64t bv[4] = {w01.x, w01.y, w23.x, w23.y};
                    // copy select: kx=0 -> O (v(q-1)), kx=1 -> E, kx=2 -> Q (v(q+1))
                    const ulonglong2* ap = (const ulonglong2*)
                        (R + ((kx == 0) ? 256 : (kx == 1) ? 0 : 512) + ty * 16);
                    #pragma unroll
                    for (int q = 0; q < 4; q++) {
                        ulonglong2 a2 = ap[q];
                        #pragma unroll
                        for (int j = 0; j < 4; j++) {
                            acc[2 * q][j]     = ffma2(a2.x, bv[j], acc[2 * q][j]);
                            acc[2 * q + 1][j] = ffma2(a2.y, bv[j], acc[2 * q + 1][j]);
                        }
                    }
                }
            }
        }
        __syncthreads();
    }

    float bj[4];
    #pragma unroll
    for (int j = 0; j < 4; j++) bj[j] = b2[oc0 + tx + 16 * j];
    #pragma unroll
    for (int i = 0; i < 8; i++) {
        int p = (ty * 8 + i) * 2;
        int l = (y << 8) + p;
        float* op0 = g_feat + (size_t)l * DIM + oc0;
        float* op1 = op0 + DIM;
        #pragma unroll
        for (int j = 0; j < 4; j++) {
            op0[tx + 16 * j] = lo_of(acc[i][j]) + bj[j];
            op1[tx + 16 * j] = hi_of(acc[i][j]) + bj[j];
        }
    }
}

// ---------------- K4: routing MLP (FFMA2 k-pair, LDS.128 b) + gumbel argmax ------
__global__ __launch_bounds__(256, 2) void k_route(const float* __restrict__ x,
                                                  const float* __restrict__ b1,
                                                  const float* __restrict__ w2,
                                                  const float* __restrict__ b2r,
                                                  const float* __restrict__ gumbel,
                                                  const float* __restrict__ emb) {
    extern __shared__ float sh[];
    float* z_s  = sh;                       // [64][196]
    u64t*  W1p  = (u64t*)(sh + 12544);      // [32][96] paired layout
    float* hm_s = sh + 12544 + 6144;        // [64][100]
    float* W2s  = sh + 25088;               // [768]
    float* lg_s = sh + 25856;               // [64][9]

    int tid = threadIdx.x;
    int l0 = blockIdx.x * 64;
    int tx = tid & 15;
    int ty = tid >> 4;

    const float4* x4 = (const float4*)(x + (size_t)l0 * DIM);
    const float4* f4 = (const float4*)(g_feat + (size_t)l0 * DIM);
    for (int idx = tid; idx < 3072; idx += 256) {
        int tok = idx / 48, c4 = idx % 48;
        float4 xv = x4[tok * 48 + c4];
        float4 fv = f4[tok * 48 + c4];
        float4 z;
        z.x = xv.x + 0.3f * fv.x; z.y = xv.y + 0.3f * fv.y;
        z.z = xv.z + 0.3f * fv.z; z.w = xv.w + 0.3f * fv.w;
        *(float4*)&z_s[tok * 196 + c4 * 4] = z;
    }
    for (int idx = tid; idx < 768; idx += 256) W2s[idx] = w2[idx];

    u64t acc[4][6];
    #pragma unroll
    for (int i = 0; i < 4; i++)
        #pragma unroll
        for (int j = 0; j < 6; j++) acc[i][j] = 0ull;

    for (int kc = 0; kc < 3; kc++) {
        __syncthreads();
        for (int idx = tid; idx < 3072; idx += 256)
            W1p[idx] = ((const u64t*)g_r1t)[kc * 3072 + idx];
        __syncthreads();
        #pragma unroll 4
        for (int kp = 0; kp < 32; kp++) {
            u64t a[4];
            #pragma unroll
            for (int i = 0; i < 4; i++)
                a[i] = *(const u64t*)&z_s[(ty * 4 + i) * 196 + kc * 64 + kp * 2];
            const ulonglong2* wp = (const ulonglong2*)&W1p[kp * 96];
            u64t bv[6];
            #pragma unroll
            for (int p = 0; p < 3; p++) {
                ulonglong2 w = wp[p * 16 + tx];
                bv[2 * p] = w.x; bv[2 * p + 1] = w.y;
            }
            #pragma unroll
            for (int j = 0; j < 6; j++)
                #pragma unroll
                for (int i = 0; i < 4; i++)
                    acc[i][j] = ffma2(a[i], bv[j], acc[i][j]);
        }
    }
    __syncthreads();
    #pragma unroll
    for (int j = 0; j < 6; j++) {
        float bb = b1[tx + 16 * j];
        #pragma unroll
        for (int i = 0; i < 4; i++) {
            float v = lohi_sum(acc[i][j]) + bb;
            v = 0.5f * v * (1.0f + erff(v * 0.7071067811865476f));
            hm_s[(ty * 4 + i) * 100 + tx + 16 * j] = v;
        }
    }
    __syncthreads();
    #pragma unroll
    for (int half = 0; half < 2; half++) {
        int tok = (tid >> 3) + half * 32;
        int t = tid & 7;
        float s = b2r[t];
        const float4* hp = (const float4*)&hm_s[tok * 100];
        const float4* wp = (const float4*)&W2s[t * 96];
        #pragma unroll 6
        for (int j4 = 0; j4 < 24; j4++) {
            float4 h = hp[j4], w = wp[j4];
            s += h.x * w.x + h.y * w.y + h.z * w.z + h.w * w.w;
        }
        lg_s[tok * 9 + t] = s;
    }
    __syncthreads();
    if (tid < 64) {
        int tok = tid;
        int l = l0 + tok;
        float mx = -1e30f;
        #pragma unroll
        for (int t = 0; t < NTOK; t++) mx = fmaxf(mx, lg_s[tok * 9 + t]);
        float e[NTOK], sum = 0.f;
        #pragma unroll
        for (int t = 0; t < NTOK; t++) { e[t] = expf(lg_s[tok * 9 + t] - mx); sum += e[t]; }
        float inv = 1.0f / sum;
        float inten = g_intensity[l];
        float best = -1e30f; int kbest = 0; float rw0 = 0.f;
        #pragma unroll
        for (int t = 0; t < NTOK; t++) {
            float rw = e[t] * inv;
            if (t == 0) rw0 = rw;
            float sim = 1.0f - fabsf(emb[t] - inten);
            float u = gumbel[(size_t)l * NTOK + t];
            u = fmaxf(u, 1e-10f);
            float g = -logf(-logf(u));
            float sc = rw * sim + g;
            if (sc > best) { best = sc; kbest = t; }
        }
        float ek = emb[kbest];
        g_gamma[l] = 0.3f + 0.7f / (1.0f + expf(-ek));
        g_beta[l]  = rw0 - 0.5f;
    }
}

// ---------------- K5: v=D*(gamma*x+beta), LayerNorm, out (LDS.128 b) -------------
__global__ __launch_bounds__(256, 2) void k_final(const float* __restrict__ x,
                                                  const float* __restrict__ Dv,
                                                  const float* __restrict__ ln_w,
                                                  const float* __restrict__ ln_b,
                                                  const float* __restrict__ out_b,
                                                  float* __restrict__ out) {
    extern __shared__ float sh[];
    float*  v_s  = sh;                           // [64][196]
    u64t*   Bs   = (u64t*)(sh + 64 * 196);       // [16][192] paired layout
    float*  mu_s = sh + 64 * 196 + 16 * 192 * 2; // [64]
    float*  rs_s = mu_s + 64;                    // [64]

    int tid = threadIdx.x;
    int l0 = blockIdx.x * 64;
    int tx = tid & 15;
    int ty = tid >> 4;

    for (int idx = tid; idx < 3072; idx += 256) {
        int tok = idx / 48, c4 = idx % 48;
        int l = l0 + tok;
        float4 xv = *(const float4*)&x[(size_t)l * DIM + c4 * 4];
        float4 dv = *(const float4*)&Dv[c4 * 4];
        float g = g_gamma[l], b = g_beta[l];
        float4 v;
        v.x = dv.x * (g * xv.x + b); v.y = dv.y * (g * xv.y + b);
        v.z = dv.z * (g * xv.z + b); v.w = dv.w * (g * xv.w + b);
        *(float4*)&v_s[tok * 196 + c4 * 4] = v;
    }
    __syncthreads();
    {
        int tok = tid >> 2, l4 = tid & 3;
        float s = 0.f, sq = 0.f;
        for (int c = l4; c < DIM; c += 4) {
            float v = v_s[tok * 196 + c];
            s += v; sq += v * v;
        }
        s  += __shfl_down_sync(0xffffffffu, s, 2);
        sq += __shfl_down_sync(0xffffffffu, sq, 2);
        s  += __shfl_down_sync(0xffffffffu, s, 1);
        sq += __shfl_down_sync(0xffffffffu, sq, 1);
        if (l4 == 0) {
            float mu = s * (1.0f / DIM);
            float var = sq * (1.0f / DIM) - mu * mu;
            mu_s[tok] = mu;
            rs_s[tok] = rsqrtf(var + 1e-5f);
        }
    }
    __syncthreads();
    for (int idx = tid; idx < 3072; idx += 256) {
        int tok = idx / 48, c4 = idx % 48;
        float4 v = *(const float4*)&v_s[tok * 196 + c4 * 4];
        float4 lw = *(const float4*)&ln_w[c4 * 4];
        float4 lb = *(const float4*)&ln_b[c4 * 4];
        float mu = mu_s[tok], rs = rs_s[tok];
        v.x = (v.x - mu) * rs * lw.x + lb.x; v.y = (v.y - mu) * rs * lw.y + lb.y;
        v.z = (v.z - mu) * rs * lw.z + lb.z; v.w = (v.w - mu) * rs * lw.w + lb.w;
        *(float4*)&v_s[tok * 196 + c4 * 4] = v;
    }

    u64t acc[4][12];
    #pragma unroll
    for (int i = 0; i < 4; i++)
        #pragma unroll
        for (int j = 0; j < 12; j++) acc[i][j] = 0ull;

    for (int kc = 0; kc < 6; kc++) {
        __syncthreads();
        for (int idx = tid; idx < 3072; idx += 256)
            Bs[idx] = ((const u64t*)g_owt)[kc * 3072 + idx];
        __syncthreads();
        #pragma unroll
        for (int kp = 0; kp < 16; kp++) {
            u64t a[4];
            #pragma unroll
            for (int i = 0; i < 4; i++)
                a[i] = *(const u64t*)&v_s[(ty * 4 + i) * 196 + kc * 32 + kp * 2];
            const ulonglong2* wp = (const ulonglong2*)&Bs[kp * 192];
            u64t bv[12];
            #pragma unroll
            for (int p = 0; p < 6; p++) {
                ulonglong2 w = wp[p * 16 + tx];
                bv[2 * p] = w.x; bv[2 * p + 1] = w.y;
            }
            #pragma unroll
            for (int j = 0; j < 12; j++)
                #pragma unroll
                for (int i = 0; i < 4; i++)
                    acc[i][j] = ffma2(a[i], bv[j], acc[i][j]);
        }
    }

    float bb[12];
    #pragma unroll
    for (int j = 0; j < 12; j++) bb[j] = out_b[tx + 16 * j];
    #pragma unroll
    for (int i = 0; i < 4; i++) {
        int l = l0 + ty * 4 + i;
        float* op = out + (size_t)l * DIM;
        #pragma unroll
        for (int j = 0; j < 12; j++)
            op[tx + 16 * j] = lohi_sum(acc[i][j]) + bb[j];
    }
}

// ---------------- launch ----------------
extern "C" void kernel_launch(void* const* d_in, const int* in_sizes, int n_in,
                              void* d_out, int out_size) {
    const float* x        = (const float*)d_in[0];
    const float* gumbel_u = (const float*)d_in[1];
    const float* conv1_w  = (const float*)d_in[2];
    const float* conv1_b  = (const float*)d_in[3];
    const float* conv2_w  = (const float*)d_in[4];
    const float* conv2_b  = (const float*)d_in[5];
    const float* route1_w = (const float*)d_in[6];
    const float* route1_b = (const float*)d_in[7];
    const float* route2_w = (const float*)d_in[8];
    const float* route2_b = (const float*)d_in[9];
    const float* Dv       = (const float*)d_in[11];
    const float* ln_w     = (const float*)d_in[12];
    const float* ln_b     = (const float*)d_in[13];
    const float* out_w    = (const float*)d_in[14];
    const float* out_b    = (const float*)d_in[15];
    const float* emb      = (const float*)d_in[16];
    float* out = (float*)d_out;

    int route_smem = (25856 + 576 + 32) * (int)sizeof(float);
    int final_smem = (64 * 196 + 16 * 192 * 2 + 128 + 16) * (int)sizeof(float);
    static int attr_done = 0;
    if (!attr_done) {
        cudaFuncSetAttribute(k_route, cudaFuncAttributeMaxDynamicSharedMemorySize, route_smem);
        cudaFuncSetAttribute(k_final, cudaFuncAttributeMaxDynamicSharedMemorySize, final_smem);
        attr_done = 1;
    }

    k_prep<<<(82944 + 18432 + 9216 + 255) / 256, 256>>>(conv2_w, out_w, route1_w);
    k_intensity<<<L_TOT / 256, 256>>>(x);
    k_conv1<<<dim3(L_TOT / 256, C1), 256>>>(conv1_w, conv1_b);
    k_conv2<<<3 * HDIM, 256>>>(conv2_b);
    k_route<<<L_TOT / 64, 256, route_smem>>>(x, route1_b, route2_w, route2_b,
                                             gumbel_u, emb);
    k_final<<<L_TOT / 64, 256, final_smem>>>(x, Dv, ln_w, ln_b, out_b, out);
}